// round 5
// baseline (speedup 1.0000x reference)
#include <cuda_runtime.h>
#include <math.h>

#define NMAX   50000
#define EMAX   1048576
#define EMB    256
#define MID    256
#define OUTD   128
#define SCAN_B 1024
#define NBLK_SCAN ((NMAX + SCAN_B - 1) / SCAN_B)   // 49

// ---- scratch (static device globals; no runtime allocation) ----
__device__ float g_H1[NMAX * MID];     // dis .* (node_emb @ W1)
__device__ float g_A1[NMAX * MID];     // gelu(agg) -> layer-2 input
__device__ float g_H2[NMAX * OUTD];    // dis .* (A1 @ W2)
__device__ float g_dis[NMAX];          // D^-1/2 (in-degree + self loop)
__device__ int   g_deg[NMAX];
__device__ int   g_rowptr[NMAX + 1];
__device__ int   g_cur[NMAX];
__device__ int   g_col[EMAX];
__device__ int   g_blocksum[NBLK_SCAN + 1];

// ----------------------------------------------------------------------------
// degree / normalization
// ----------------------------------------------------------------------------
__global__ void zero_deg_kernel(int n) {
    int i = blockIdx.x * blockDim.x + threadIdx.x;
    if (i < n) g_deg[i] = 0;
}

__global__ void count_deg_kernel(const int* __restrict__ dst, int E) {
    int e = blockIdx.x * blockDim.x + threadIdx.x;
    if (e < E) atomicAdd(&g_deg[dst[e]], 1);
}

__global__ void compute_dis_kernel(int n) {
    int i = blockIdx.x * blockDim.x + threadIdx.x;
    if (i < n) g_dis[i] = rsqrtf((float)(g_deg[i] + 1));  // +1 = self loop
}

// ----------------------------------------------------------------------------
// multi-block exclusive scan of g_deg -> g_rowptr
// ----------------------------------------------------------------------------
__global__ __launch_bounds__(SCAN_B)
void scan_phase1_kernel(int n) {
    __shared__ int s[SCAN_B];
    int i = blockIdx.x * SCAN_B + threadIdx.x;
    int v = (i < n) ? g_deg[i] : 0;
    s[threadIdx.x] = v;
    __syncthreads();
#pragma unroll
    for (int off = 1; off < SCAN_B; off <<= 1) {
        int t = (threadIdx.x >= off) ? s[threadIdx.x - off] : 0;
        __syncthreads();
        s[threadIdx.x] += t;
        __syncthreads();
    }
    if (i < n) g_rowptr[i] = s[threadIdx.x] - v;
    if (threadIdx.x == SCAN_B - 1) g_blocksum[blockIdx.x] = s[SCAN_B - 1];
}

__global__ __launch_bounds__(64)
void scan_phase2_kernel(int nblk) {
    __shared__ int s[64];
    int v = (threadIdx.x < nblk) ? g_blocksum[threadIdx.x] : 0;
    s[threadIdx.x] = v;
    __syncthreads();
#pragma unroll
    for (int off = 1; off < 64; off <<= 1) {
        int t = (threadIdx.x >= off) ? s[threadIdx.x - off] : 0;
        __syncthreads();
        s[threadIdx.x] += t;
        __syncthreads();
    }
    if (threadIdx.x < nblk) g_blocksum[threadIdx.x] = s[threadIdx.x] - v;
    if (threadIdx.x == 63) g_blocksum[nblk] = s[63];
}

__global__ __launch_bounds__(SCAN_B)
void scan_phase3_kernel(int n, int nblk) {
    int i = blockIdx.x * SCAN_B + threadIdx.x;
    if (i < n) {
        int ex = g_rowptr[i] + g_blocksum[blockIdx.x];
        g_rowptr[i] = ex;
        g_cur[i] = ex;
    }
    if (i == 0) g_rowptr[n] = g_blocksum[nblk];
}

// ----------------------------------------------------------------------------
// CSR fill
// ----------------------------------------------------------------------------
__global__ void fill_csr_kernel(const int* __restrict__ src,
                                const int* __restrict__ dst, int E) {
    int e = blockIdx.x * blockDim.x + threadIdx.x;
    if (e < E) {
        int d = dst[e];
        int pos = atomicAdd(&g_cur[d], 1);
        g_col[pos] = src[e];
    }
}

// ----------------------------------------------------------------------------
// 3xTF32 tensor-core GEMM with row-scale epilogue:
//   C[m,:] = dis[m] * (A @ B)[m,:]
// BM=128, BN=64, BK=16; 256 threads (8 warps, 4x2 warp grid, 32x32 per warp).
// fp32 emulated via hi/lo split: C = Ah*Bh + Ah*Bl + Al*Bh  (~1e-6 rel err)
// ----------------------------------------------------------------------------
#define BM 128
#define BN 64
#define BK 16
#define ASTR 20   // BK+4: frag-load banks (20g+t) mod 32 all-distinct
#define BSTR 72   // BN+8: frag-load banks (8t+g) mod 32 all-distinct

__device__ __forceinline__ float tf32_trunc(float x) {
    return __uint_as_float(__float_as_uint(x) & 0xFFFFE000u);
}

__device__ __forceinline__ void mma_tf32(float* d, const float* a, const float* b) {
    asm volatile(
        "mma.sync.aligned.m16n8k8.row.col.f32.tf32.tf32.f32 "
        "{%0,%1,%2,%3}, {%4,%5,%6,%7}, {%8,%9}, {%0,%1,%2,%3};\n"
        : "+f"(d[0]), "+f"(d[1]), "+f"(d[2]), "+f"(d[3])
        : "r"(__float_as_uint(a[0])), "r"(__float_as_uint(a[1])),
          "r"(__float_as_uint(a[2])), "r"(__float_as_uint(a[3])),
          "r"(__float_as_uint(b[0])), "r"(__float_as_uint(b[1])));
}

__global__ __launch_bounds__(256)
void gemm_tf32_scale_kernel(const float* __restrict__ A, const float* __restrict__ B,
                            float* __restrict__ C, int M, int N, int K) {
    __shared__ float Ah[BM][ASTR];
    __shared__ float Al[BM][ASTR];
    __shared__ float Bh[BK][BSTR];
    __shared__ float Bl[BK][BSTR];

    int tid  = threadIdx.x;
    int lane = tid & 31;
    int wid  = tid >> 5;          // 0..7
    int gID  = lane >> 2;         // 0..7
    int tig  = lane & 3;          // 0..3
    int warpM = wid >> 1;         // 0..3 -> 32-row slab
    int warpN = wid & 1;          // 0..1 -> 32-col slab

    int m0 = blockIdx.y * BM;
    int n0 = blockIdx.x * BN;

    // loader indices
    int aRow = tid >> 1;          // 0..127
    int akk  = (tid & 1) * 8;     // 0 or 8
    int bK   = tid >> 4;          // 0..15
    int bn   = (tid & 15) * 4;    // 0..60

    float acc[2][4][4];
#pragma unroll
    for (int mt = 0; mt < 2; mt++)
#pragma unroll
        for (int nt = 0; nt < 4; nt++)
#pragma unroll
            for (int r = 0; r < 4; r++) acc[mt][nt][r] = 0.0f;

    int nC = K / BK;

    float4 pa0, pa1, pb;
    // prefetch chunk 0
    {
        int gm = m0 + aRow;
        if (gm < M) {
            const float* ap = A + (size_t)gm * K + akk;
            pa0 = *(const float4*)(ap);
            pa1 = *(const float4*)(ap + 4);
        } else {
            pa0 = pa1 = make_float4(0.f, 0.f, 0.f, 0.f);
        }
        pb = *(const float4*)(B + (size_t)bK * N + n0 + bn);
    }

    for (int c = 0; c < nC; c++) {
        // ---- store prefetched chunk to smem (hi/lo split) ----
        {
            float va[8] = {pa0.x, pa0.y, pa0.z, pa0.w, pa1.x, pa1.y, pa1.z, pa1.w};
#pragma unroll
            for (int j = 0; j < 8; j++) {
                float hi = tf32_trunc(va[j]);
                Ah[aRow][akk + j] = hi;
                Al[aRow][akk + j] = va[j] - hi;
            }
            float vb[4] = {pb.x, pb.y, pb.z, pb.w};
#pragma unroll
            for (int j = 0; j < 4; j++) {
                float hi = tf32_trunc(vb[j]);
                Bh[bK][bn + j] = hi;
                Bl[bK][bn + j] = vb[j] - hi;
            }
        }
        __syncthreads();

        // ---- prefetch next chunk ----
        if (c + 1 < nC) {
            int k0 = (c + 1) * BK;
            int gm = m0 + aRow;
            if (gm < M) {
                const float* ap = A + (size_t)gm * K + k0 + akk;
                pa0 = *(const float4*)(ap);
                pa1 = *(const float4*)(ap + 4);
            } else {
                pa0 = pa1 = make_float4(0.f, 0.f, 0.f, 0.f);
            }
            pb = *(const float4*)(B + (size_t)(k0 + bK) * N + n0 + bn);
        }

        // ---- compute: kk in {0, 8} ----
#pragma unroll
        for (int kk = 0; kk < BK; kk += 8) {
            float ah[2][4], al[2][4];
#pragma unroll
            for (int mt = 0; mt < 2; mt++) {
                int r = warpM * 32 + mt * 16 + gID;
                ah[mt][0] = Ah[r][kk + tig];
                ah[mt][1] = Ah[r + 8][kk + tig];
                ah[mt][2] = Ah[r][kk + tig + 4];
                ah[mt][3] = Ah[r + 8][kk + tig + 4];
                al[mt][0] = Al[r][kk + tig];
                al[mt][1] = Al[r + 8][kk + tig];
                al[mt][2] = Al[r][kk + tig + 4];
                al[mt][3] = Al[r + 8][kk + tig + 4];
            }
            float bh[4][2], bl[4][2];
#pragma unroll
            for (int nt = 0; nt < 4; nt++) {
                int n = warpN * 32 + nt * 8 + gID;
                bh[nt][0] = Bh[kk + tig][n];
                bh[nt][1] = Bh[kk + tig + 4][n];
                bl[nt][0] = Bl[kk + tig][n];
                bl[nt][1] = Bl[kk + tig + 4][n];
            }
#pragma unroll
            for (int mt = 0; mt < 2; mt++)
#pragma unroll
                for (int nt = 0; nt < 4; nt++) {
                    mma_tf32(acc[mt][nt], ah[mt], bh[nt]);
                    mma_tf32(acc[mt][nt], ah[mt], bl[nt]);
                    mma_tf32(acc[mt][nt], al[mt], bh[nt]);
                }
        }
        __syncthreads();
    }

    // ---- epilogue: scale by dis[row], store ----
#pragma unroll
    for (int mt = 0; mt < 2; mt++) {
        int row0 = m0 + warpM * 32 + mt * 16 + gID;
        int row1 = row0 + 8;
        float s0 = (row0 < M) ? g_dis[row0] : 0.0f;
        float s1 = (row1 < M) ? g_dis[row1] : 0.0f;
#pragma unroll
        for (int nt = 0; nt < 4; nt++) {
            int col = n0 + warpN * 32 + nt * 8 + tig * 2;
            if (row0 < M) {
                float2 v = {acc[mt][nt][0] * s0, acc[mt][nt][1] * s0};
                *(float2*)(C + (size_t)row0 * N + col) = v;
            }
            if (row1 < M) {
                float2 v = {acc[mt][nt][2] * s1, acc[mt][nt][3] * s1};
                *(float2*)(C + (size_t)row1 * N + col) = v;
            }
        }
    }
}

// ----------------------------------------------------------------------------
// pull aggregation + bias + exact GELU
// ----------------------------------------------------------------------------
__device__ __forceinline__ float4 f4add(float4 a, float4 b) {
    return make_float4(a.x + b.x, a.y + b.y, a.z + b.z, a.w + b.w);
}

template <int TPG>
__global__ __launch_bounds__(256)
void agg_gelu_kernel(const float* __restrict__ Hs, const float* __restrict__ bias,
                     float* __restrict__ Out, int n) {
    int gid = (int)(blockIdx.x * blockDim.x + threadIdx.x) / TPG;
    int t   = threadIdx.x & (TPG - 1);
    if (gid >= n) return;

    const float4* H4 = (const float4*)Hs;
    int beg = g_rowptr[gid];
    int end = g_rowptr[gid + 1];

    float4 a0 = H4[(size_t)gid * TPG + t];
    float4 a1 = make_float4(0.f, 0.f, 0.f, 0.f);
    float4 a2 = a1, a3 = a1;

    int p = beg;
    for (; p + 3 < end; p += 4) {
        int s0 = g_col[p];
        int s1 = g_col[p + 1];
        int s2 = g_col[p + 2];
        int s3 = g_col[p + 3];
        a0 = f4add(a0, H4[(size_t)s0 * TPG + t]);
        a1 = f4add(a1, H4[(size_t)s1 * TPG + t]);
        a2 = f4add(a2, H4[(size_t)s2 * TPG + t]);
        a3 = f4add(a3, H4[(size_t)s3 * TPG + t]);
    }
    for (; p < end; p++)
        a0 = f4add(a0, H4[(size_t)g_col[p] * TPG + t]);

    float4 acc = f4add(f4add(a0, a1), f4add(a2, a3));
    float dd = g_dis[gid];
    float4 bb = ((const float4*)bias)[t];

    float x0 = acc.x * dd + bb.x;
    float x1 = acc.y * dd + bb.y;
    float x2 = acc.z * dd + bb.z;
    float x3 = acc.w * dd + bb.w;
    const float inv_sqrt2 = 0.70710678118654752f;
    float4 o;
    o.x = 0.5f * x0 * (1.0f + erff(x0 * inv_sqrt2));
    o.y = 0.5f * x1 * (1.0f + erff(x1 * inv_sqrt2));
    o.z = 0.5f * x2 * (1.0f + erff(x2 * inv_sqrt2));
    o.w = 0.5f * x3 * (1.0f + erff(x3 * inv_sqrt2));
    ((float4*)Out)[(size_t)gid * TPG + t] = o;
}

// ----------------------------------------------------------------------------
extern "C" void kernel_launch(void* const* d_in, const int* in_sizes, int n_in,
                              void* d_out, int out_size) {
    const float* node_emb = (const float*)d_in[0];   // [N, 256]
    const float* W1       = (const float*)d_in[1];   // [256, 256]
    const float* b1       = (const float*)d_in[2];   // [256]
    const float* W2       = (const float*)d_in[3];   // [256, 128]
    const float* b2       = (const float*)d_in[4];   // [128]
    const int*   eidx     = (const int*)d_in[5];     // [2, E]

    int N = in_sizes[0] / EMB;
    int E = in_sizes[5] / 2;
    const int* src = eidx;
    const int* dst = eidx + E;

    float* H1 = nullptr; float* A1 = nullptr; float* H2 = nullptr;
    cudaGetSymbolAddress((void**)&H1, g_H1);
    cudaGetSymbolAddress((void**)&A1, g_A1);
    cudaGetSymbolAddress((void**)&H2, g_H2);
    float* outp = (float*)d_out;

    int nblk_scan = (N + SCAN_B - 1) / SCAN_B;

    // ---- degrees, normalization, CSR ----
    zero_deg_kernel<<<(N + 255) / 256, 256>>>(N);
    count_deg_kernel<<<(E + 255) / 256, 256>>>(dst, E);
    compute_dis_kernel<<<(N + 255) / 256, 256>>>(N);
    scan_phase1_kernel<<<nblk_scan, SCAN_B>>>(N);
    scan_phase2_kernel<<<1, 64>>>(nblk_scan);
    scan_phase3_kernel<<<nblk_scan, SCAN_B>>>(N, nblk_scan);
    fill_csr_kernel<<<(E + 255) / 256, 256>>>(src, dst, E);

    // ---- layer 1 ----
    {
        dim3 grid(MID / BN, (N + BM - 1) / BM);
        gemm_tf32_scale_kernel<<<grid, 256>>>(node_emb, W1, H1, N, MID, EMB);
    }
    {
        const int TPG = MID / 4;
        int groups_per_blk = 256 / TPG;
        int nblk = (N + groups_per_blk - 1) / groups_per_blk;
        agg_gelu_kernel<TPG><<<nblk, 256>>>(H1, b1, A1, N);
    }

    // ---- layer 2 ----
    {
        dim3 grid(OUTD / BN, (N + BM - 1) / BM);
        gemm_tf32_scale_kernel<<<grid, 256>>>(A1, W2, H2, N, OUTD, MID);
    }
    {
        const int TPG = OUTD / 4;
        int groups_per_blk = 256 / TPG;
        int nblk = (N + groups_per_blk - 1) / groups_per_blk;
        agg_gelu_kernel<TPG><<<nblk, 256>>>(H2, b2, outp, N);
    }
}

// round 6
// speedup vs baseline: 1.1000x; 1.1000x over previous
#include <cuda_runtime.h>
#include <math.h>

#define NMAX   50000
#define EMAX   1048576
#define EMB    256
#define MID    256
#define OUTD   128
#define SCAN_B 1024
#define NBLK_SCAN ((NMAX + SCAN_B - 1) / SCAN_B)   // 49

// ---- scratch (static device globals; no runtime allocation) ----
__device__ float g_H1[NMAX * MID];     // dis .* (node_emb @ W1)
__device__ float g_A1[NMAX * MID];     // gelu(agg) -> layer-2 input
__device__ float g_H2[NMAX * OUTD];    // dis .* (A1 @ W2)
__device__ float g_dis[NMAX];          // D^-1/2 (in-degree + self loop)
__device__ int   g_deg[NMAX];
__device__ int   g_rowptr[NMAX + 1];
__device__ int   g_cur[NMAX];
__device__ int   g_col[EMAX];
__device__ int   g_blocksum[NBLK_SCAN + 1];

// ----------------------------------------------------------------------------
// degree / normalization
// ----------------------------------------------------------------------------
__global__ void zero_deg_kernel(int n) {
    int i = blockIdx.x * blockDim.x + threadIdx.x;
    if (i < n) g_deg[i] = 0;
}

__global__ void count_deg_kernel(const int* __restrict__ dst, int E) {
    int e = blockIdx.x * blockDim.x + threadIdx.x;
    if (e < E) atomicAdd(&g_deg[dst[e]], 1);
}

__global__ void compute_dis_kernel(int n) {
    int i = blockIdx.x * blockDim.x + threadIdx.x;
    if (i < n) g_dis[i] = rsqrtf((float)(g_deg[i] + 1));  // +1 = self loop
}

// ----------------------------------------------------------------------------
// multi-block exclusive scan of g_deg -> g_rowptr
// ----------------------------------------------------------------------------
__global__ __launch_bounds__(SCAN_B)
void scan_phase1_kernel(int n) {
    __shared__ int s[SCAN_B];
    int i = blockIdx.x * SCAN_B + threadIdx.x;
    int v = (i < n) ? g_deg[i] : 0;
    s[threadIdx.x] = v;
    __syncthreads();
#pragma unroll
    for (int off = 1; off < SCAN_B; off <<= 1) {
        int t = (threadIdx.x >= off) ? s[threadIdx.x - off] : 0;
        __syncthreads();
        s[threadIdx.x] += t;
        __syncthreads();
    }
    if (i < n) g_rowptr[i] = s[threadIdx.x] - v;
    if (threadIdx.x == SCAN_B - 1) g_blocksum[blockIdx.x] = s[SCAN_B - 1];
}

__global__ __launch_bounds__(64)
void scan_phase2_kernel(int nblk) {
    __shared__ int s[64];
    int v = (threadIdx.x < nblk) ? g_blocksum[threadIdx.x] : 0;
    s[threadIdx.x] = v;
    __syncthreads();
#pragma unroll
    for (int off = 1; off < 64; off <<= 1) {
        int t = (threadIdx.x >= off) ? s[threadIdx.x - off] : 0;
        __syncthreads();
        s[threadIdx.x] += t;
        __syncthreads();
    }
    if (threadIdx.x < nblk) g_blocksum[threadIdx.x] = s[threadIdx.x] - v;
    if (threadIdx.x == 63) g_blocksum[nblk] = s[63];
}

__global__ __launch_bounds__(SCAN_B)
void scan_phase3_kernel(int n, int nblk) {
    int i = blockIdx.x * SCAN_B + threadIdx.x;
    if (i < n) {
        int ex = g_rowptr[i] + g_blocksum[blockIdx.x];
        g_rowptr[i] = ex;
        g_cur[i] = ex;
    }
    if (i == 0) g_rowptr[n] = g_blocksum[nblk];
}

// ----------------------------------------------------------------------------
// CSR fill
// ----------------------------------------------------------------------------
__global__ void fill_csr_kernel(const int* __restrict__ src,
                                const int* __restrict__ dst, int E) {
    int e = blockIdx.x * blockDim.x + threadIdx.x;
    if (e < E) {
        int d = dst[e];
        int pos = atomicAdd(&g_cur[d], 1);
        g_col[pos] = src[e];
    }
}

// ----------------------------------------------------------------------------
// 3xTF32 tensor-core GEMM, hi/lo interleaved smem (LDS.64 fragment loads):
//   C[m,:] = dis[m] * (A @ B)[m,:]
// BM=128, BN=64, BK=16; 256 threads (8 warps, 4x2 warp grid, 32x32 per warp).
// ----------------------------------------------------------------------------
#define BM 128
#define BN 64
#define BK 16
#define ASTR2 40    // floats per A row: 2*BK + 8  -> conflict-free LDS.64 frag loads
#define BSTR2 136   // floats per B row: 2*BN + 8  -> conflict-free LDS.64 frag loads

__device__ __forceinline__ float tf32_trunc(float x) {
    return __uint_as_float(__float_as_uint(x) & 0xFFFFE000u);
}

__device__ __forceinline__ void mma_tf32(float* d, const float* a, const float* b) {
    asm volatile(
        "mma.sync.aligned.m16n8k8.row.col.f32.tf32.tf32.f32 "
        "{%0,%1,%2,%3}, {%4,%5,%6,%7}, {%8,%9}, {%0,%1,%2,%3};\n"
        : "+f"(d[0]), "+f"(d[1]), "+f"(d[2]), "+f"(d[3])
        : "r"(__float_as_uint(a[0])), "r"(__float_as_uint(a[1])),
          "r"(__float_as_uint(a[2])), "r"(__float_as_uint(a[3])),
          "r"(__float_as_uint(b[0])), "r"(__float_as_uint(b[1])));
}

__global__ __launch_bounds__(256)
void gemm_tf32_scale_kernel(const float* __restrict__ A, const float* __restrict__ B,
                            float* __restrict__ C, int M, int N, int K) {
    __shared__ float Ahl[BM][ASTR2];   // [row][2k]=hi, [2k+1]=lo   (20.5 KB)
    __shared__ float Bhl[BK][BSTR2];   // [k][2n]=hi, [2n+1]=lo     (8.7 KB)

    int tid  = threadIdx.x;
    int lane = tid & 31;
    int wid  = tid >> 5;          // 0..7
    int gID  = lane >> 2;         // 0..7
    int tig  = lane & 3;          // 0..3
    int warpM = wid >> 1;         // 0..3 -> 32-row slab
    int warpN = wid & 1;          // 0..1 -> 32-col slab

    int m0 = blockIdx.y * BM;
    int n0 = blockIdx.x * BN;

    // loader indices
    int aRow = tid >> 1;          // 0..127
    int akk  = (tid & 1) * 8;     // 0 or 8
    int bK   = tid >> 4;          // 0..15
    int bn   = (tid & 15) * 4;    // 0..60

    float acc[2][4][4];
#pragma unroll
    for (int mt = 0; mt < 2; mt++)
#pragma unroll
        for (int nt = 0; nt < 4; nt++)
#pragma unroll
            for (int r = 0; r < 4; r++) acc[mt][nt][r] = 0.0f;

    int nC = K / BK;

    float4 pa0, pa1, pb;
    // prefetch chunk 0
    {
        int gm = m0 + aRow;
        if (gm < M) {
            const float* ap = A + (size_t)gm * K + akk;
            pa0 = *(const float4*)(ap);
            pa1 = *(const float4*)(ap + 4);
        } else {
            pa0 = pa1 = make_float4(0.f, 0.f, 0.f, 0.f);
        }
        pb = *(const float4*)(B + (size_t)bK * N + n0 + bn);
    }

    for (int c = 0; c < nC; c++) {
        // ---- store prefetched chunk to smem (hi/lo interleaved) ----
        {
            float va[8] = {pa0.x, pa0.y, pa0.z, pa0.w, pa1.x, pa1.y, pa1.z, pa1.w};
#pragma unroll
            for (int j = 0; j < 8; j++) {
                float hi = tf32_trunc(va[j]);
                *(float2*)&Ahl[aRow][2 * (akk + j)] = make_float2(hi, va[j] - hi);
            }
            float vb[4] = {pb.x, pb.y, pb.z, pb.w};
#pragma unroll
            for (int j = 0; j < 4; j++) {
                float hi = tf32_trunc(vb[j]);
                *(float2*)&Bhl[bK][2 * (bn + j)] = make_float2(hi, vb[j] - hi);
            }
        }
        __syncthreads();

        // ---- prefetch next chunk ----
        if (c + 1 < nC) {
            int k0 = (c + 1) * BK;
            int gm = m0 + aRow;
            if (gm < M) {
                const float* ap = A + (size_t)gm * K + k0 + akk;
                pa0 = *(const float4*)(ap);
                pa1 = *(const float4*)(ap + 4);
            } else {
                pa0 = pa1 = make_float4(0.f, 0.f, 0.f, 0.f);
            }
            pb = *(const float4*)(B + (size_t)(k0 + bK) * N + n0 + bn);
        }

        // ---- compute: kk in {0, 8} ----
#pragma unroll
        for (int kk = 0; kk < BK; kk += 8) {
            float ah[2][4], al[2][4];
#pragma unroll
            for (int mt = 0; mt < 2; mt++) {
                int r = warpM * 32 + mt * 16 + gID;
                float2 q0 = *(const float2*)&Ahl[r][2 * (kk + tig)];
                float2 q1 = *(const float2*)&Ahl[r + 8][2 * (kk + tig)];
                float2 q2 = *(const float2*)&Ahl[r][2 * (kk + tig + 4)];
                float2 q3 = *(const float2*)&Ahl[r + 8][2 * (kk + tig + 4)];
                ah[mt][0] = q0.x; al[mt][0] = q0.y;
                ah[mt][1] = q1.x; al[mt][1] = q1.y;
                ah[mt][2] = q2.x; al[mt][2] = q2.y;
                ah[mt][3] = q3.x; al[mt][3] = q3.y;
            }
            float bh[4][2], bl[4][2];
#pragma unroll
            for (int nt = 0; nt < 4; nt++) {
                int n = warpN * 32 + nt * 8 + gID;
                float2 p0 = *(const float2*)&Bhl[kk + tig][2 * n];
                float2 p1 = *(const float2*)&Bhl[kk + tig + 4][2 * n];
                bh[nt][0] = p0.x; bl[nt][0] = p0.y;
                bh[nt][1] = p1.x; bl[nt][1] = p1.y;
            }
#pragma unroll
            for (int mt = 0; mt < 2; mt++)
#pragma unroll
                for (int nt = 0; nt < 4; nt++) {
                    mma_tf32(acc[mt][nt], ah[mt], bh[nt]);
                    mma_tf32(acc[mt][nt], ah[mt], bl[nt]);
                    mma_tf32(acc[mt][nt], al[mt], bh[nt]);
                }
        }
        __syncthreads();
    }

    // ---- epilogue: scale by dis[row], store ----
#pragma unroll
    for (int mt = 0; mt < 2; mt++) {
        int row0 = m0 + warpM * 32 + mt * 16 + gID;
        int row1 = row0 + 8;
        float s0 = (row0 < M) ? g_dis[row0] : 0.0f;
        float s1 = (row1 < M) ? g_dis[row1] : 0.0f;
#pragma unroll
        for (int nt = 0; nt < 4; nt++) {
            int col = n0 + warpN * 32 + nt * 8 + tig * 2;
            if (row0 < M) {
                float2 v = {acc[mt][nt][0] * s0, acc[mt][nt][1] * s0};
                *(float2*)(C + (size_t)row0 * N + col) = v;
            }
            if (row1 < M) {
                float2 v = {acc[mt][nt][2] * s1, acc[mt][nt][3] * s1};
                *(float2*)(C + (size_t)row1 * N + col) = v;
            }
        }
    }
}

// ----------------------------------------------------------------------------
// pull aggregation + bias + exact GELU
// ----------------------------------------------------------------------------
__device__ __forceinline__ float4 f4add(float4 a, float4 b) {
    return make_float4(a.x + b.x, a.y + b.y, a.z + b.z, a.w + b.w);
}

template <int TPG>
__global__ __launch_bounds__(256)
void agg_gelu_kernel(const float* __restrict__ Hs, const float* __restrict__ bias,
                     float* __restrict__ Out, int n) {
    int gid = (int)(blockIdx.x * blockDim.x + threadIdx.x) / TPG;
    int t   = threadIdx.x & (TPG - 1);
    if (gid >= n) return;

    const float4* H4 = (const float4*)Hs;
    int beg = g_rowptr[gid];
    int end = g_rowptr[gid + 1];

    float4 a0 = H4[(size_t)gid * TPG + t];
    float4 a1 = make_float4(0.f, 0.f, 0.f, 0.f);
    float4 a2 = a1, a3 = a1;

    int p = beg;
    for (; p + 3 < end; p += 4) {
        int s0 = g_col[p];
        int s1 = g_col[p + 1];
        int s2 = g_col[p + 2];
        int s3 = g_col[p + 3];
        a0 = f4add(a0, H4[(size_t)s0 * TPG + t]);
        a1 = f4add(a1, H4[(size_t)s1 * TPG + t]);
        a2 = f4add(a2, H4[(size_t)s2 * TPG + t]);
        a3 = f4add(a3, H4[(size_t)s3 * TPG + t]);
    }
    for (; p < end; p++)
        a0 = f4add(a0, H4[(size_t)g_col[p] * TPG + t]);

    float4 acc = f4add(f4add(a0, a1), f4add(a2, a3));
    float dd = g_dis[gid];
    float4 bb = ((const float4*)bias)[t];

    float x0 = acc.x * dd + bb.x;
    float x1 = acc.y * dd + bb.y;
    float x2 = acc.z * dd + bb.z;
    float x3 = acc.w * dd + bb.w;
    const float inv_sqrt2 = 0.70710678118654752f;
    float4 o;
    o.x = 0.5f * x0 * (1.0f + erff(x0 * inv_sqrt2));
    o.y = 0.5f * x1 * (1.0f + erff(x1 * inv_sqrt2));
    o.z = 0.5f * x2 * (1.0f + erff(x2 * inv_sqrt2));
    o.w = 0.5f * x3 * (1.0f + erff(x3 * inv_sqrt2));
    ((float4*)Out)[(size_t)gid * TPG + t] = o;
}

// ----------------------------------------------------------------------------
extern "C" void kernel_launch(void* const* d_in, const int* in_sizes, int n_in,
                              void* d_out, int out_size) {
    const float* node_emb = (const float*)d_in[0];   // [N, 256]
    const float* W1       = (const float*)d_in[1];   // [256, 256]
    const float* b1       = (const float*)d_in[2];   // [256]
    const float* W2       = (const float*)d_in[3];   // [256, 128]
    const float* b2       = (const float*)d_in[4];   // [128]
    const int*   eidx     = (const int*)d_in[5];     // [2, E]

    int N = in_sizes[0] / EMB;
    int E = in_sizes[5] / 2;
    const int* src = eidx;
    const int* dst = eidx + E;

    float* H1 = nullptr; float* A1 = nullptr; float* H2 = nullptr;
    cudaGetSymbolAddress((void**)&H1, g_H1);
    cudaGetSymbolAddress((void**)&A1, g_A1);
    cudaGetSymbolAddress((void**)&H2, g_H2);
    float* outp = (float*)d_out;

    int nblk_scan = (N + SCAN_B - 1) / SCAN_B;

    // ---- degrees, normalization, CSR ----
    zero_deg_kernel<<<(N + 255) / 256, 256>>>(N);
    count_deg_kernel<<<(E + 255) / 256, 256>>>(dst, E);
    compute_dis_kernel<<<(N + 255) / 256, 256>>>(N);
    scan_phase1_kernel<<<nblk_scan, SCAN_B>>>(N);
    scan_phase2_kernel<<<1, 64>>>(nblk_scan);
    scan_phase3_kernel<<<nblk_scan, SCAN_B>>>(N, nblk_scan);
    fill_csr_kernel<<<(E + 255) / 256, 256>>>(src, dst, E);

    // ---- layer 1 ----
    {
        dim3 grid(MID / BN, (N + BM - 1) / BM);
        gemm_tf32_scale_kernel<<<grid, 256>>>(node_emb, W1, H1, N, MID, EMB);
    }
    {
        const int TPG = MID / 4;
        int groups_per_blk = 256 / TPG;
        int nblk = (N + groups_per_blk - 1) / groups_per_blk;
        agg_gelu_kernel<TPG><<<nblk, 256>>>(H1, b1, A1, N);
    }

    // ---- layer 2 ----
    {
        dim3 grid(OUTD / BN, (N + BM - 1) / BM);
        gemm_tf32_scale_kernel<<<grid, 256>>>(A1, W2, H2, N, OUTD, MID);
    }
    {
        const int TPG = OUTD / 4;
        int groups_per_blk = 256 / TPG;
        int nblk = (N + groups_per_blk - 1) / groups_per_blk;
        agg_gelu_kernel<TPG><<<nblk, 256>>>(H2, b2, outp, N);
    }
}

// round 9
// speedup vs baseline: 1.4199x; 1.2908x over previous
#include <cuda_runtime.h>
#include <cuda_bf16.h>
#include <math.h>
#include <stdint.h>

#define NMAX   50000
#define EMAX   1048576
#define EMB    256
#define MID    256
#define OUTD   128
#define SCAN_B 1024
#define NBLK_SCAN ((NMAX + SCAN_B - 1) / SCAN_B)   // 49

// ---- scratch (static device globals; no runtime allocation) ----
__device__ float g_H1[NMAX * MID];     // dis .* (node_emb @ W1)
__device__ float g_A1[NMAX * MID];     // gelu(agg) -> layer-2 input
__device__ float g_H2[NMAX * OUTD];    // dis .* (A1 @ W2)
__device__ float g_dis[NMAX];          // D^-1/2 (in-degree + self loop)
__device__ int   g_deg[NMAX];
__device__ int   g_rowptr[NMAX + 1];
__device__ int   g_cur[NMAX];
__device__ int   g_col[EMAX];
__device__ int   g_blocksum[NBLK_SCAN + 1];

// ----------------------------------------------------------------------------
// degree / normalization
// ----------------------------------------------------------------------------
__global__ void zero_deg_kernel(int n) {
    int i = blockIdx.x * blockDim.x + threadIdx.x;
    if (i < n) g_deg[i] = 0;
}

__global__ void count_deg_kernel(const int* __restrict__ dst, int E) {
    int e = blockIdx.x * blockDim.x + threadIdx.x;
    if (e < E) atomicAdd(&g_deg[dst[e]], 1);
}

__global__ void compute_dis_kernel(int n) {
    int i = blockIdx.x * blockDim.x + threadIdx.x;
    if (i < n) g_dis[i] = rsqrtf((float)(g_deg[i] + 1));  // +1 = self loop
}

// ----------------------------------------------------------------------------
// multi-block exclusive scan of g_deg -> g_rowptr
// ----------------------------------------------------------------------------
__global__ __launch_bounds__(SCAN_B)
void scan_phase1_kernel(int n) {
    __shared__ int s[SCAN_B];
    int i = blockIdx.x * SCAN_B + threadIdx.x;
    int v = (i < n) ? g_deg[i] : 0;
    s[threadIdx.x] = v;
    __syncthreads();
#pragma unroll
    for (int off = 1; off < SCAN_B; off <<= 1) {
        int t = (threadIdx.x >= off) ? s[threadIdx.x - off] : 0;
        __syncthreads();
        s[threadIdx.x] += t;
        __syncthreads();
    }
    if (i < n) g_rowptr[i] = s[threadIdx.x] - v;
    if (threadIdx.x == SCAN_B - 1) g_blocksum[blockIdx.x] = s[SCAN_B - 1];
}

__global__ __launch_bounds__(64)
void scan_phase2_kernel(int nblk) {
    __shared__ int s[64];
    int v = (threadIdx.x < nblk) ? g_blocksum[threadIdx.x] : 0;
    s[threadIdx.x] = v;
    __syncthreads();
#pragma unroll
    for (int off = 1; off < 64; off <<= 1) {
        int t = (threadIdx.x >= off) ? s[threadIdx.x - off] : 0;
        __syncthreads();
        s[threadIdx.x] += t;
        __syncthreads();
    }
    if (threadIdx.x < nblk) g_blocksum[threadIdx.x] = s[threadIdx.x] - v;
    if (threadIdx.x == 63) g_blocksum[nblk] = s[63];
}

__global__ __launch_bounds__(SCAN_B)
void scan_phase3_kernel(int n, int nblk) {
    int i = blockIdx.x * SCAN_B + threadIdx.x;
    if (i < n) {
        int ex = g_rowptr[i] + g_blocksum[blockIdx.x];
        g_rowptr[i] = ex;
        g_cur[i] = ex;
    }
    if (i == 0) g_rowptr[n] = g_blocksum[nblk];
}

// ----------------------------------------------------------------------------
// CSR fill
// ----------------------------------------------------------------------------
__global__ void fill_csr_kernel(const int* __restrict__ src,
                                const int* __restrict__ dst, int E) {
    int e = blockIdx.x * blockDim.x + threadIdx.x;
    if (e < E) {
        int d = dst[e];
        int pos = atomicAdd(&g_cur[d], 1);
        g_col[pos] = src[e];
    }
}

// ----------------------------------------------------------------------------
// 3x-bf16 mma.sync GEMM (m16n8k16), hi/mid packed uint2 in smem:
//   C[m,:] = dis[m] * (A @ B)[m,:]
// BM=128, BN=64, BK=16; 256 threads (8 warps, 4x2 warp grid, 32x32 per warp).
// C = Ah*Bh + Ah*Bm + Am*Bh, fp32 accum. Split: hi=bf16(x), mid=bf16(x-hi).
// ----------------------------------------------------------------------------
#define BM 128
#define BN 64
#define BK 16
#define ASTR 12   // uint2 per A row (8 kpairs used): (g*12+tig) mod 16 distinct
#define BSTR 68   // uint2 per B kpair row (64 n used): (tig*68+n) mod 16 distinct

__device__ __forceinline__ uint32_t pack_bf16x2(float lo_k, float hi_k) {
    // lower 16 bits = element with lower k index
    __nv_bfloat162 p = __nv_bfloat162(__float2bfloat16(lo_k), __float2bfloat16(hi_k));
    return *(uint32_t*)&p;
}

__device__ __forceinline__ void split2(float f0, float f1, uint32_t& hi, uint32_t& mid) {
    __nv_bfloat16 h0 = __float2bfloat16(f0);
    __nv_bfloat16 h1 = __float2bfloat16(f1);
    float r0 = f0 - __bfloat162float(h0);
    float r1 = f1 - __bfloat162float(h1);
    __nv_bfloat162 hp = __nv_bfloat162(h0, h1);
    __nv_bfloat162 mp = __nv_bfloat162(__float2bfloat16(r0), __float2bfloat16(r1));
    hi  = *(uint32_t*)&hp;
    mid = *(uint32_t*)&mp;
}

__device__ __forceinline__ void mma_bf16(float* d, const uint32_t* a, const uint32_t* b) {
    asm volatile(
        "mma.sync.aligned.m16n8k16.row.col.f32.bf16.bf16.f32 "
        "{%0,%1,%2,%3}, {%4,%5,%6,%7}, {%8,%9}, {%0,%1,%2,%3};\n"
        : "+f"(d[0]), "+f"(d[1]), "+f"(d[2]), "+f"(d[3])
        : "r"(a[0]), "r"(a[1]), "r"(a[2]), "r"(a[3]),
          "r"(b[0]), "r"(b[1]));
}

__global__ __launch_bounds__(256)
void gemm_bf16_scale_kernel(const float* __restrict__ A, const float* __restrict__ B,
                            float* __restrict__ C, int M, int N, int K) {
    // Ahl[row][kp] = {hi bf16x2, mid bf16x2} for k = 2kp, 2kp+1
    __shared__ uint2 Ahl[BM][ASTR];    // 12 KB
    __shared__ uint2 Bhl[BK / 2][BSTR]; // 4.25 KB

    int tid  = threadIdx.x;
    int lane = tid & 31;
    int wid  = tid >> 5;          // 0..7
    int gID  = lane >> 2;         // 0..7
    int tig  = lane & 3;          // 0..3
    int warpM = wid >> 1;         // 0..3 -> 32-row slab
    int warpN = wid & 1;          // 0..1 -> 32-col slab

    int m0 = blockIdx.y * BM;
    int n0 = blockIdx.x * BN;

    // A loader: row = tid>>1, 8 consecutive k (4 kpairs)
    int aRow = tid >> 1;          // 0..127
    int akk  = (tid & 1) * 8;     // 0 or 8
    int akp  = (tid & 1) * 4;     // kpair base 0 or 4
    // B loader (tid < 128): kpair = tid>>4 (0..7), 4 n columns
    int bkp  = (tid & 127) >> 4;  // 0..7
    int bn   = (tid & 15) * 4;    // 0..60

    float acc[2][4][4];
#pragma unroll
    for (int mt = 0; mt < 2; mt++)
#pragma unroll
        for (int nt = 0; nt < 4; nt++)
#pragma unroll
            for (int r = 0; r < 4; r++) acc[mt][nt][r] = 0.0f;

    int nC = K / BK;

    float4 pa0, pa1, pb0, pb1;
    // prefetch chunk 0
    {
        int gm = m0 + aRow;
        if (gm < M) {
            const float* ap = A + (size_t)gm * K + akk;
            pa0 = *(const float4*)(ap);
            pa1 = *(const float4*)(ap + 4);
        } else {
            pa0 = pa1 = make_float4(0.f, 0.f, 0.f, 0.f);
        }
        if (tid < 128) {
            const float* bp = B + (size_t)(2 * bkp) * N + n0 + bn;
            pb0 = *(const float4*)(bp);
            pb1 = *(const float4*)(bp + N);
        }
    }

    for (int c = 0; c < nC; c++) {
        // ---- store prefetched chunk to smem (bf16 hi/mid split) ----
        {
            float va[8] = {pa0.x, pa0.y, pa0.z, pa0.w, pa1.x, pa1.y, pa1.z, pa1.w};
#pragma unroll
            for (int j = 0; j < 4; j++) {
                uint32_t hi, mid;
                split2(va[2 * j], va[2 * j + 1], hi, mid);
                Ahl[aRow][akp + j] = make_uint2(hi, mid);
            }
            if (tid < 128) {
                float b0[4] = {pb0.x, pb0.y, pb0.z, pb0.w};   // k = 2*bkp
                float b1[4] = {pb1.x, pb1.y, pb1.z, pb1.w};   // k = 2*bkp+1
#pragma unroll
                for (int j = 0; j < 4; j++) {
                    uint32_t hi, mid;
                    split2(b0[j], b1[j], hi, mid);
                    Bhl[bkp][bn + j] = make_uint2(hi, mid);
                }
            }
        }
        __syncthreads();

        // ---- prefetch next chunk ----
        if (c + 1 < nC) {
            int k0 = (c + 1) * BK;
            int gm = m0 + aRow;
            if (gm < M) {
                const float* ap = A + (size_t)gm * K + k0 + akk;
                pa0 = *(const float4*)(ap);
                pa1 = *(const float4*)(ap + 4);
            } else {
                pa0 = pa1 = make_float4(0.f, 0.f, 0.f, 0.f);
            }
            if (tid < 128) {
                const float* bp = B + (size_t)(k0 + 2 * bkp) * N + n0 + bn;
                pb0 = *(const float4*)(bp);
                pb1 = *(const float4*)(bp + N);
            }
        }

        // ---- compute: one m16n8k16 k-step covers BK=16 ----
        {
            uint32_t ah[2][4], am[2][4];
#pragma unroll
            for (int mt = 0; mt < 2; mt++) {
                int r = warpM * 32 + mt * 16 + gID;
                uint2 q0 = Ahl[r][tig];            // a0: row g,   kp tig
                uint2 q1 = Ahl[r + 8][tig];        // a1: row g+8, kp tig
                uint2 q2 = Ahl[r][tig + 4];        // a2: row g,   kp tig+4
                uint2 q3 = Ahl[r + 8][tig + 4];    // a3: row g+8, kp tig+4
                ah[mt][0] = q0.x; am[mt][0] = q0.y;
                ah[mt][1] = q1.x; am[mt][1] = q1.y;
                ah[mt][2] = q2.x; am[mt][2] = q2.y;
                ah[mt][3] = q3.x; am[mt][3] = q3.y;
            }
            uint32_t bh[4][2], bm[4][2];
#pragma unroll
            for (int nt = 0; nt < 4; nt++) {
                int n = warpN * 32 + nt * 8 + gID;
                uint2 p0 = Bhl[tig][n];            // b0: kp tig
                uint2 p1 = Bhl[tig + 4][n];        // b1: kp tig+4
                bh[nt][0] = p0.x; bm[nt][0] = p0.y;
                bh[nt][1] = p1.x; bm[nt][1] = p1.y;
            }
#pragma unroll
            for (int mt = 0; mt < 2; mt++)
#pragma unroll
                for (int nt = 0; nt < 4; nt++) {
                    mma_bf16(acc[mt][nt], ah[mt], bh[nt]);
                    mma_bf16(acc[mt][nt], ah[mt], bm[nt]);
                    mma_bf16(acc[mt][nt], am[mt], bh[nt]);
                }
        }
        __syncthreads();
    }

    // ---- epilogue: scale by dis[row], store ----
#pragma unroll
    for (int mt = 0; mt < 2; mt++) {
        int row0 = m0 + warpM * 32 + mt * 16 + gID;
        int row1 = row0 + 8;
        float s0 = (row0 < M) ? g_dis[row0] : 0.0f;
        float s1 = (row1 < M) ? g_dis[row1] : 0.0f;
#pragma unroll
        for (int nt = 0; nt < 4; nt++) {
            int col = n0 + warpN * 32 + nt * 8 + tig * 2;
            if (row0 < M) {
                float2 v = {acc[mt][nt][0] * s0, acc[mt][nt][1] * s0};
                *(float2*)(C + (size_t)row0 * N + col) = v;
            }
            if (row1 < M) {
                float2 v = {acc[mt][nt][2] * s1, acc[mt][nt][3] * s1};
                *(float2*)(C + (size_t)row1 * N + col) = v;
            }
        }
    }
}

// ----------------------------------------------------------------------------
// pull aggregation + bias + exact GELU
// ----------------------------------------------------------------------------
__device__ __forceinline__ float4 f4add(float4 a, float4 b) {
    return make_float4(a.x + b.x, a.y + b.y, a.z + b.z, a.w + b.w);
}

template <int TPG>
__global__ __launch_bounds__(256)
void agg_gelu_kernel(const float* __restrict__ Hs, const float* __restrict__ bias,
                     float* __restrict__ Out, int n) {
    int gid = (int)(blockIdx.x * blockDim.x + threadIdx.x) / TPG;
    int t   = threadIdx.x & (TPG - 1);
    if (gid >= n) return;

    const float4* H4 = (const float4*)Hs;
    int beg = g_rowptr[gid];
    int end = g_rowptr[gid + 1];

    float4 a0 = H4[(size_t)gid * TPG + t];
    float4 a1 = make_float4(0.f, 0.f, 0.f, 0.f);
    float4 a2 = a1, a3 = a1;

    int p = beg;
    for (; p + 3 < end; p += 4) {
        int s0 = g_col[p];
        int s1 = g_col[p + 1];
        int s2 = g_col[p + 2];
        int s3 = g_col[p + 3];
        a0 = f4add(a0, H4[(size_t)s0 * TPG + t]);
        a1 = f4add(a1, H4[(size_t)s1 * TPG + t]);
        a2 = f4add(a2, H4[(size_t)s2 * TPG + t]);
        a3 = f4add(a3, H4[(size_t)s3 * TPG + t]);
    }
    for (; p < end; p++)
        a0 = f4add(a0, H4[(size_t)g_col[p] * TPG + t]);

    float4 acc = f4add(f4add(a0, a1), f4add(a2, a3));
    float dd = g_dis[gid];
    float4 bb = ((const float4*)bias)[t];

    float x0 = acc.x * dd + bb.x;
    float x1 = acc.y * dd + bb.y;
    float x2 = acc.z * dd + bb.z;
    float x3 = acc.w * dd + bb.w;
    const float inv_sqrt2 = 0.70710678118654752f;
    float4 o;
    o.x = 0.5f * x0 * (1.0f + erff(x0 * inv_sqrt2));
    o.y = 0.5f * x1 * (1.0f + erff(x1 * inv_sqrt2));
    o.z = 0.5f * x2 * (1.0f + erff(x2 * inv_sqrt2));
    o.w = 0.5f * x3 * (1.0f + erff(x3 * inv_sqrt2));
    ((float4*)Out)[(size_t)gid * TPG + t] = o;
}

// ----------------------------------------------------------------------------
extern "C" void kernel_launch(void* const* d_in, const int* in_sizes, int n_in,
                              void* d_out, int out_size) {
    const float* node_emb = (const float*)d_in[0];   // [N, 256]
    const float* W1       = (const float*)d_in[1];   // [256, 256]
    const float* b1       = (const float*)d_in[2];   // [256]
    const float* W2       = (const float*)d_in[3];   // [256, 128]
    const float* b2       = (const float*)d_in[4];   // [128]
    const int*   eidx     = (const int*)d_in[5];     // [2, E]

    int N = in_sizes[0] / EMB;
    int E = in_sizes[5] / 2;
    const int* src = eidx;
    const int* dst = eidx + E;

    float* H1 = nullptr; float* A1 = nullptr; float* H2 = nullptr;
    cudaGetSymbolAddress((void**)&H1, g_H1);
    cudaGetSymbolAddress((void**)&A1, g_A1);
    cudaGetSymbolAddress((void**)&H2, g_H2);
    float* outp = (float*)d_out;

    int nblk_scan = (N + SCAN_B - 1) / SCAN_B;

    // ---- degrees, normalization, CSR ----
    zero_deg_kernel<<<(N + 255) / 256, 256>>>(N);
    count_deg_kernel<<<(E + 255) / 256, 256>>>(dst, E);
    compute_dis_kernel<<<(N + 255) / 256, 256>>>(N);
    scan_phase1_kernel<<<nblk_scan, SCAN_B>>>(N);
    scan_phase2_kernel<<<1, 64>>>(nblk_scan);
    scan_phase3_kernel<<<nblk_scan, SCAN_B>>>(N, nblk_scan);
    fill_csr_kernel<<<(E + 255) / 256, 256>>>(src, dst, E);

    // ---- layer 1 ----
    {
        dim3 grid(MID / BN, (N + BM - 1) / BM);
        gemm_bf16_scale_kernel<<<grid, 256>>>(node_emb, W1, H1, N, MID, EMB);
    }
    {
        const int TPG = MID / 4;
        int groups_per_blk = 256 / TPG;
        int nblk = (N + groups_per_blk - 1) / groups_per_blk;
        agg_gelu_kernel<TPG><<<nblk, 256>>>(H1, b1, A1, N);
    }

    // ---- layer 2 ----
    {
        dim3 grid(OUTD / BN, (N + BM - 1) / BM);
        gemm_bf16_scale_kernel<<<grid, 256>>>(A1, W2, H2, N, OUTD, MID);
    }
    {
        const int TPG = OUTD / 4;
        int groups_per_blk = 256 / TPG;
        int nblk = (N + groups_per_blk - 1) / groups_per_blk;
        agg_gelu_kernel<TPG><<<nblk, 256>>>(H2, b2, outp, N);
    }
}